// round 10
// baseline (speedup 1.0000x reference)
#include <cuda_runtime.h>
#include <cstdint>
#include <cstring>

#define NTOT 2048
#define JROWS 288
#define EPSV 1e-6f
#define LN2F 0.6931471805599453f
#define IL2F 1.4426950408889634f

typedef unsigned int  u32;
typedef unsigned long long u64;
typedef unsigned short u16;

// ---------------- fp32 scratch ----------------
static __device__ __align__(16) float g_part[524288];
static __device__ __align__(16) float g_Hraw[NTOT * 128];
static __device__ __align__(16) float g_H   [NTOT * 128];
static __device__ __align__(16) float g_logH[NTOT * 128];   // log2(H)
static __device__ __align__(16) float g_jpart[JROWS * 128];
static __device__ __align__(16) float g_w   [128];

// ---------------- bf16 split scratch ----------------
static __device__ __align__(16) u16 XCH[524288], XCL[524288];   // x combined [2048][256]: cols 0:128 xt, 128:256 xn
static __device__ __align__(16) u16 XTH[524288], XTL[524288];   // x^T per side [128][2048]
static __device__ __align__(16) u16 W1TH[1048576], W1TL[1048576]; // W1^T per head [128][2048]
static __device__ __align__(16) u16 W2TH[65536],  W2TL[65536];
static __device__ __align__(16) u16 BGTH[65536],  BGTL[65536];  // fW1 permuted: [side][128][256]
static __device__ __align__(16) u16 FW2TH[16384], FW2TL[16384];
static __device__ __align__(16) u16 THTH[32768],  THTL[32768];
static __device__ __align__(16) u16 MAH[65536],   MAL[65536];   // M combined: [side][128][256]
static __device__ __align__(16) u16 P1H[65536],   P1L[65536];
static __device__ __align__(16) u16 GTCH[32768],  GTCL[32768];  // G^T combined [128][256]
static __device__ __align__(16) u16 HTMH[262144], HTML[262144];
static __device__ __align__(16) u16 HH [262144],  HL [262144];
static __device__ __align__(16) u16 HTH[262144],  HTL[262144];  // H^T [128][2048]
static __device__ __align__(16) u16 YTH[524288],  YTL[524288];  // Y^T per side [128][2048]
static __device__ __align__(16) u16 ZWTH[32768],  ZWTL[32768];

// ---------------- bf16 helpers ----------------
__device__ __forceinline__ u16 f2bf(float v) {
    u32 x = __float_as_uint(v);
    x += 0x7FFFu + ((x >> 16) & 1u);
    return (u16)(x >> 16);
}
__device__ __forceinline__ float bf2f(u16 h) { return __uint_as_float(((u32)h) << 16); }
__device__ __forceinline__ void bf_split(float v, u16& h, u16& l) {
    h = f2bf(v); l = f2bf(v - bf2f(h));
}

// ---------------- PTX helpers ----------------
__device__ __forceinline__ u32 smem_u32(const void* p) {
    u32 a;
    asm("{ .reg .u64 t; cvta.to.shared.u64 t, %1; cvt.u32.u64 %0, t; }" : "=r"(a) : "l"(p));
    return a;
}
#define SW128(o) ((o) ^ (((o) >> 3) & 0x70))
#define CP16(dst, src) asm volatile("cp.async.cg.shared.global [%0], [%1], 16;" :: "r"(dst), "l"(src) : "memory")
#define CP_COMMIT() asm volatile("cp.async.commit_group;" ::: "memory")
#define CP_WAIT1() asm volatile("cp.async.wait_group 1;" ::: "memory")
#define CP_WAIT0() asm volatile("cp.async.wait_group 0;" ::: "memory")

__device__ __forceinline__ void ldm4(u32* r, u32 addr) {
    asm volatile("ldmatrix.sync.aligned.m8n8.x4.shared.b16 {%0,%1,%2,%3}, [%4];"
                 : "=r"(r[0]), "=r"(r[1]), "=r"(r[2]), "=r"(r[3]) : "r"(addr));
}
__device__ __forceinline__ void mmabf(float* c, const u32* a, u32 b0, u32 b1) {
    asm volatile("mma.sync.aligned.m16n8k16.row.col.f32.bf16.bf16.f32 "
        "{%0,%1,%2,%3}, {%4,%5,%6,%7}, {%8,%9}, {%0,%1,%2,%3};"
        : "+f"(c[0]), "+f"(c[1]), "+f"(c[2]), "+f"(c[3])
        : "r"(a[0]), "r"(a[1]), "r"(a[2]), "r"(a[3]), "r"(b0), "r"(b1));
}

// ================= generic tensor-core GEMM =================
// D[128,128](fp32) = sum_k (AH+AL)[m,k]*(BH+BL)[n,k] (3 split products), K-major ops.
// grid (Mtiles, Kchunks, Z), 256 threads (8 warps, each 64x32 out block).
// modes: 0 fp32 split-K partial | 2 transposed bf16 | 4 fp32 + aux[c]
//        5 fp32 aux-residual + elu | 6 bf16 row-major + aux[c] | 7 bf16 row-major relu(v+aux[c])
struct MmaP {
    const u16 *AH[4], *AL[4], *BH[4], *BL[4];
    float* outF[4];
    u16 *oH[4], *oL[4];
    const float* aux[4];
    int ldA, ldB, ldO, Kchunk, chunkStride, mode;
};

__global__ void __launch_bounds__(256) k_mma(MmaP p) {
    extern __shared__ __align__(16) char dyn[];
    u32 sbase = smem_u32(dyn);

    int z = blockIdx.z, by = blockIdx.y;
    int mBase = blockIdx.x * 128;
    int kBeg = by * p.Kchunk;
    int nslab = p.Kchunk >> 5;
    int tid = threadIdx.x, lane = tid & 31, wid = tid >> 5;
    int wm = wid & 1, wn = wid >> 1;

    // loader role: threads 0-127 load A rows, 128-255 load B rows
    int lrow = tid & 127;
    bool isA = tid < 128;
    const u16* srcH = isA ? p.AH[z] + (size_t)(mBase + lrow) * p.ldA + kBeg
                          : p.BH[z] + (size_t)lrow * p.ldB + kBeg;
    const u16* srcL = isA ? p.AL[z] + (size_t)(mBase + lrow) * p.ldA + kBeg
                          : p.BL[z] + (size_t)lrow * p.ldB + kBeg;
    u32 bufOff = isA ? 0u : 16384u;
    u32 rowo = (u32)lrow * 128u;

    float acc[4][4][4];
#pragma unroll
    for (int t = 0; t < 4; t++)
#pragma unroll
        for (int n = 0; n < 4; n++)
#pragma unroll
            for (int q = 0; q < 4; q++) acc[t][n][q] = 0.f;

    auto LDGA = [&](int s, int buf) {
        u32 b = sbase + (u32)buf * 32768u + bufOff;
        const u16* sh = srcH + (size_t)s * 32;
        const u16* sl = srcL + (size_t)s * 32;
#pragma unroll
        for (int j = 0; j < 4; j++) {
            CP16(b + SW128(rowo + (u32)j * 16u), sh + j * 8);
            CP16(b + SW128(rowo + 64u + (u32)j * 16u), sl + j * 8);
        }
    };
    auto COMPUTE = [&](int buf) {
        u32 tA = sbase + (u32)buf * 32768u;
        u32 tB = tA + 16384u;
#pragma unroll
        for (int kk = 0; kk < 2; kk++) {
            u32 colh = (u32)kk * 32u + (u32)((lane >> 4) << 4);
            u32 bh[8], bl[8];
#pragma unroll
            for (int pp = 0; pp < 2; pp++) {
                u32 nr = (u32)(wn * 32 + pp * 16 + (lane & 15));
                ldm4(bh + pp * 4, tB + SW128(nr * 128u + colh));
                ldm4(bl + pp * 4, tB + SW128(nr * 128u + 64u + colh));
            }
#pragma unroll
            for (int t = 0; t < 4; t++) {
                u32 ah[4], al[4];
                u32 mr = (u32)(wm * 64 + t * 16 + (lane & 15));
                ldm4(ah, tA + SW128(mr * 128u + colh));
                ldm4(al, tA + SW128(mr * 128u + 64u + colh));
                mmabf(acc[t][0], ah, bh[0], bh[2]);
                mmabf(acc[t][0], ah, bl[0], bl[2]);
                mmabf(acc[t][0], al, bh[0], bh[2]);
                mmabf(acc[t][1], ah, bh[1], bh[3]);
                mmabf(acc[t][1], ah, bl[1], bl[3]);
                mmabf(acc[t][1], al, bh[1], bh[3]);
                mmabf(acc[t][2], ah, bh[4], bh[6]);
                mmabf(acc[t][2], ah, bl[4], bl[6]);
                mmabf(acc[t][2], al, bh[4], bh[6]);
                mmabf(acc[t][3], ah, bh[5], bh[7]);
                mmabf(acc[t][3], ah, bl[5], bl[7]);
                mmabf(acc[t][3], al, bh[5], bh[7]);
            }
        }
    };

    LDGA(0, 0); CP_COMMIT();
#pragma unroll 1
    for (int s = 0; s < nslab; s++) {
        if (s + 1 < nslab) { LDGA(s + 1, (s + 1) & 1); CP_COMMIT(); CP_WAIT1(); }
        else CP_WAIT0();
        __syncthreads();
        COMPUTE(s & 1);
        __syncthreads();
    }

    // ---------- dump acc -> smem fp32 [128][129] ----------
    float* smF = (float*)dyn;
#pragma unroll
    for (int t = 0; t < 4; t++)
#pragma unroll
        for (int n = 0; n < 4; n++) {
            int r = wm * 64 + t * 16 + (lane >> 2);
            int c = wn * 32 + n * 8 + ((lane & 3) << 1);
            smF[r * 129 + c]           = acc[t][n][0];
            smF[r * 129 + c + 1]       = acc[t][n][1];
            smF[(r + 8) * 129 + c]     = acc[t][n][2];
            smF[(r + 8) * 129 + c + 1] = acc[t][n][3];
        }
    __syncthreads();

    // ---------- writeback ----------
    if (p.mode == 2) {                         // transposed bf16 split
#pragma unroll 4
        for (int q = 0; q < 64; q++) {
            int idx = q * 256 + tid;
            int r = idx & 127, n = idx >> 7;
            float v = smF[r * 129 + n];
            u16 h, l; bf_split(v, h, l);
            size_t o = (size_t)n * p.ldO + mBase + r;
            p.oH[z][o] = h; p.oL[z][o] = l;
        }
    } else {
#pragma unroll 4
        for (int q = 0; q < 64; q++) {
            int idx = q * 256 + tid;
            int r = idx >> 7, c = idx & 127;
            float v = smF[r * 129 + c];
            size_t grow = (size_t)(mBase + r);
            if (p.mode == 0) {
                p.outF[z][(size_t)by * p.chunkStride + grow * 128 + c] = v;
            } else if (p.mode == 4) {
                p.outF[z][grow * 128 + c] = v + p.aux[z][c];
            } else if (p.mode == 5) {
                float x = p.aux[z][grow * 128 + c];
                p.outF[z][grow * 128 + c] = x + ((v > 0.f) ? v : expm1f(v));
            } else if (p.mode == 6) {
                v += p.aux[z][c];
                u16 h, l; bf_split(v, h, l);
                p.oH[z][grow * p.ldO + c] = h; p.oL[z][grow * p.ldO + c] = l;
            } else {                           // 7: relu(v+aux) bf16 row-major
                v = fmaxf(v + p.aux[z][c], 0.f);
                u16 h, l; bf_split(v, h, l);
                p.oH[z][grow * p.ldO + c] = h; p.oL[z][grow * p.ldO + c] = l;
            }
        }
    }
}

// ================= transpose + bf16-split conversion =================
__device__ __forceinline__ void tconv(const float* __restrict__ src, int tileRow,
                                      u16* dH, u16* dL, int dLd,
                                      u16* tH, u16* tL, int tLd)
{
    __shared__ u16 sh[32][136], sl[32][136];
    int tid = threadIdx.x;
    for (int i = tid; i < 32 * 128; i += 256) {
        int r = i >> 7, c = i & 127;
        float v = src[(size_t)(tileRow + r) * 128 + c];
        u16 h, l; bf_split(v, h, l);
        if (dH) { dH[(size_t)(tileRow + r) * dLd + c] = h; dL[(size_t)(tileRow + r) * dLd + c] = l; }
        sh[r][c] = h; sl[r][c] = l;
    }
    __syncthreads();
    for (int i = tid; i < 128 * 32; i += 256) {
        int rt = i >> 5, ct = i & 31;
        size_t o = (size_t)rt * tLd + tileRow + ct;
        tH[o] = sh[ct][rt]; tL[o] = sl[ct][rt];
    }
}

__global__ __launch_bounds__(256) void k_convX(const float* __restrict__ xt, const float* __restrict__ xn)
{
    int side = blockIdx.y;
    const float* src = side ? xn : xt;
    tconv(src, blockIdx.x * 32,
          XCH + side * 128, XCL + side * 128, 256,
          XTH + (size_t)side * 262144, XTL + (size_t)side * 262144, 2048);
}

struct WPtrs { const float* s[12]; };
__global__ __launch_bounds__(256) void k_convW(WPtrs wp)
{
    const int tilesC[13] = {0, 64, 128, 192, 256, 260, 264, 268, 272, 288, 292, 296, 300};
    int b = blockIdx.x, idx = 0;
    while (b >= tilesC[idx + 1]) idx++;
    int lt = b - tilesC[idx];

    if (idx == 8) {
        // fW1 -> BGT permuted: BGT[side][b][slot], side = head&1, slot = (head>>1)*128 + pos
        __shared__ u16 sh[32][136], sl[32][136];
        int tid = threadIdx.x;
        int tileRow = lt * 32;
        const float* src = wp.s[8];
        for (int i = tid; i < 32 * 128; i += 256) {
            int r = i >> 7, c = i & 127;
            float v = src[(size_t)(tileRow + r) * 128 + c];
            u16 h, l; bf_split(v, h, l);
            sh[r][c] = h; sl[r][c] = l;
        }
        __syncthreads();
        for (int i = tid; i < 128 * 32; i += 256) {
            int bb = i >> 5, ct = i & 31;
            int k = tileRow + ct;
            int head = k >> 7, pos = k & 127;
            int side = head & 1;
            int slot = ((head >> 1) << 7) + pos;
            size_t o = (size_t)side * 32768 + (size_t)bb * 256 + slot;
            BGTH[o] = sh[ct][bb]; BGTL[o] = sl[ct][bb];
        }
        return;
    }

    u16 *tH, *tL; int K;
    if (idx < 4)      { K = 2048; tH = W1TH + (size_t)idx * 262144;      tL = W1TL + (size_t)idx * 262144; }
    else if (idx < 8) { K = 128;  tH = W2TH + (idx - 4) * 16384; tL = W2TL + (idx - 4) * 16384; }
    else if (idx == 9){ K = 128;  tH = FW2TH;                    tL = FW2TL; }
    else              { K = 128;  tH = THTH + (idx - 10) * 16384; tL = THTL + (idx - 10) * 16384; }
    tconv(wp.s[idx], lt * 32, nullptr, nullptr, 0, tH, tL, K);
}

__global__ __launch_bounds__(256) void k_convH()
{
    tconv(g_H, blockIdx.x * 32, HH, HL, 128, HTH, HTL, 2048);
}

// ================= reductions =================
__global__ __launch_bounds__(256) void k_redP1(const float* __restrict__ b0, const float* __restrict__ b1,
                                               const float* __restrict__ b2, const float* __restrict__ b3)
{
    int z = blockIdx.y;
    int i = blockIdx.x * 256 + threadIdx.x;              // < 16384
    const float* b = (z == 0) ? b0 : (z == 1) ? b1 : (z == 2) ? b2 : b3;
    float s = b[i & 127];
#pragma unroll
    for (int c = 0; c < 8; c++) s += g_part[(size_t)z * 131072 + (size_t)c * 16384 + i];
    s = fmaxf(s, 0.f);
    u16 h, l; bf_split(s, h, l);
    P1H[z * 16384 + i] = h; P1L[z * 16384 + i] = l;
}

__global__ __launch_bounds__(256) void k_redZW()
{
    int z = blockIdx.y;
    int i = blockIdx.x * 256 + threadIdx.x;              // < 16384
    float s = 0.f;
#pragma unroll
    for (int c = 0; c < 8; c++) s += g_part[(size_t)z * 131072 + (size_t)c * 16384 + i];
    s *= g_w[i & 127];
    u16 h, l; bf_split(s, h, l);
    ZWTH[z * 16384 + i] = h; ZWTL[z * 16384 + i] = l;
}

// ================= block reductions =================
template <int NW>
__device__ __forceinline__ float block_sum(float v) {
    __shared__ float sred[8];
    __syncthreads();
#pragma unroll
    for (int o = 16; o; o >>= 1) v += __shfl_xor_sync(0xffffffffu, v, o);
    if ((threadIdx.x & 31) == 0) sred[threadIdx.x >> 5] = v;
    __syncthreads();
    float t = 0.f;
#pragma unroll
    for (int k = 0; k < NW; k++) t += sred[k];
    return t;
}
template <int NW>
__device__ __forceinline__ float block_max(float v) {
    __shared__ float sred[8];
    __syncthreads();
#pragma unroll
    for (int o = 16; o; o >>= 1) v = fmaxf(v, __shfl_xor_sync(0xffffffffu, v, o));
    if ((threadIdx.x & 31) == 0) sred[threadIdx.x >> 5] = v;
    __syncthreads();
    float t = -3.4e38f;
#pragma unroll
    for (int k = 0; k < NW; k++) t = fmaxf(t, sred[k]);
    return t;
}

// ================= column standardize + softmax (logH stored as log2) =================
__global__ __launch_bounds__(256) void k_colsm()
{
    int e = blockIdx.x;
    __shared__ float s[NTOT];
    int tid = threadIdx.x;
    for (int n = tid; n < NTOT; n += 256) s[n] = g_Hraw[n * 128 + e];
    __syncthreads();
    float lsum = 0.f;
    for (int n = tid; n < NTOT; n += 256) lsum += s[n];
    float mean = block_sum<8>(lsum) * (1.f / NTOT);
    float lss = 0.f;
    for (int n = tid; n < NTOT; n += 256) { float d = s[n] - mean; lss += d * d; }
    float var = block_sum<8>(lss) * (1.f / (NTOT - 1));
    float inv = 1.f / (sqrtf(var) + EPSV);
    float lmax = -3.4e38f;
    for (int n = tid; n < NTOT; n += 256) {
        float z = (s[n] - mean) * inv;
        s[n] = z;
        lmax = fmaxf(lmax, z);
    }
    __syncthreads();
    float mx = block_max<8>(lmax);
    float lse = 0.f;
    for (int n = tid; n < NTOT; n += 256) lse += __expf(s[n] - mx);
    float sum = block_sum<8>(lse);
    float invs = 1.f / sum;
    float l2s = __log2f(sum);
    for (int n = tid; n < NTOT; n += 256) {
        float z = s[n];
        g_H[n * 128 + e]    = __expf(z - mx) * invs;
        g_logH[n * 128 + e] = (z - mx) * IL2F - l2s;     // log2(H)
    }
}

// ================= pairwise JSD (log2 domain) =================
__global__ __launch_bounds__(256) void k_jsd()
{
    int t = blockIdx.x;
    int bi = 0, rem = t;
    while (rem >= 8 - bi) { rem -= 8 - bi; bi++; }
    int bj = bi + rem;
    int tid = threadIdx.x;
    int ti = tid & 15, tj = tid >> 4;
    int i = bi * 16 + ti, j = bj * 16 + tj;
    __shared__ float sHi[16][16], sLi[16][16], sHj[16][16], sLj[16][16];
    float acci = 0.f, accj = 0.f;
    int lr = tid >> 4, lc = tid & 15;
    int nBeg = blockIdx.y * 256;
    for (int n0 = nBeg; n0 < nBeg + 256; n0 += 16) {
        __syncthreads();
        int n = n0 + lr;
        sHi[lr][lc] = g_H   [n * 128 + bi * 16 + lc];
        sLi[lr][lc] = g_logH[n * 128 + bi * 16 + lc];
        sHj[lr][lc] = g_H   [n * 128 + bj * 16 + lc];
        sLj[lr][lc] = g_logH[n * 128 + bj * 16 + lc];
        __syncthreads();
#pragma unroll
        for (int r = 0; r < 16; r++) {
            float hi = sHi[r][ti], hj = sHj[r][tj];
            float m  = 0.5f * (hi + hj);
            float lm = __log2f(m);
            acci += hi * (sLi[r][ti] - lm);
            accj += hj * (sLj[r][tj] - lm);
        }
    }
    float v = (i < j) ? 0.5f * LN2F * (acci + accj) : 0.f;
    __shared__ float red[16][16];
    __syncthreads();
    red[tj][ti] = v;
    __syncthreads();
    float* out = g_jpart + (size_t)(blockIdx.y * 36 + blockIdx.x) * 128;
    if (tid < 128) out[tid] = 0.f;
    __syncthreads();
    if (tid < 16) {
        float si = 0.f, sj = 0.f;
#pragma unroll
        for (int r = 0; r < 16; r++) { si += red[r][tid]; sj += red[tid][r]; }
        out[bi * 16 + tid] += si;
        out[bj * 16 + tid] += sj;
    }
}

__global__ __launch_bounds__(128) void k_w()
{
    int e = threadIdx.x;
    float cs = 0.f;
    for (int r = 0; r < JROWS; r++) cs += g_jpart[r * 128 + e];
    float jm = cs * (1.f / 128.f);
    float mean = block_sum<4>(jm) * (1.f / 128.f);
    float d = jm - mean;
    float var = block_sum<4>(d * d) * (1.f / 127.f);
    float njm = d / (sqrtf(var) + EPSV);
    float mx = block_max<4>(njm);
    float ex = __expf(njm - mx);
    float sum = block_sum<4>(ex);
    g_w[e] = ex / sum;
}

// ================= host =================
static inline void* dsym(const void* s) { void* p = nullptr; cudaGetSymbolAddress(&p, s); return p; }

extern "C" void kernel_launch(void* const* d_in, const int* in_sizes, int n_in,
                              void* d_out, int out_size)
{
    const float* xt  = (const float*)d_in[0];
    const float* xn  = (const float*)d_in[1];
    const float* W1[4]  = {(const float*)d_in[2],  (const float*)d_in[6],  (const float*)d_in[10], (const float*)d_in[14]};
    const float* B1[4]  = {(const float*)d_in[3],  (const float*)d_in[7],  (const float*)d_in[11], (const float*)d_in[15]};
    const float* W2[4]  = {(const float*)d_in[4],  (const float*)d_in[8],  (const float*)d_in[12], (const float*)d_in[16]};
    const float* B2[4]  = {(const float*)d_in[5],  (const float*)d_in[9],  (const float*)d_in[13], (const float*)d_in[17]};
    const float* fW1 = (const float*)d_in[18];
    const float* fb1 = (const float*)d_in[19];
    const float* fW2 = (const float*)d_in[20];
    const float* fb2 = (const float*)d_in[21];
    const float* thT = (const float*)d_in[22];
    const float* thN = (const float*)d_in[23];
    float* out = (float*)d_out;

    static const int SMEM = 66560;
    cudaFuncSetAttribute(k_mma, cudaFuncAttributeMaxDynamicSharedMemorySize, SMEM);

    u16 *xch = (u16*)dsym(XCH), *xcl = (u16*)dsym(XCL), *xth = (u16*)dsym(XTH), *xtl = (u16*)dsym(XTL);
    u16 *w1h = (u16*)dsym(W1TH), *w1l = (u16*)dsym(W1TL), *w2h = (u16*)dsym(W2TH), *w2l = (u16*)dsym(W2TL);
    u16 *bgh = (u16*)dsym(BGTH), *bgl = (u16*)dsym(BGTL), *f2h = (u16*)dsym(FW2TH), *f2l = (u16*)dsym(FW2TL);
    u16 *thh = (u16*)dsym(THTH), *thl = (u16*)dsym(THTL);
    u16 *mah = (u16*)dsym(MAH), *mal = (u16*)dsym(MAL), *p1h = (u16*)dsym(P1H), *p1l = (u16*)dsym(P1L);
    u16 *gth = (u16*)dsym(GTCH), *gtl = (u16*)dsym(GTCL), *htmh = (u16*)dsym(HTMH), *html = (u16*)dsym(HTML);
    u16 *hh = (u16*)dsym(HH), *hl = (u16*)dsym(HL), *hth = (u16*)dsym(HTH), *htl = (u16*)dsym(HTL);
    u16 *yth = (u16*)dsym(YTH), *ytl = (u16*)dsym(YTL), *zwh = (u16*)dsym(ZWTH), *zwl = (u16*)dsym(ZWTL);
    float* gp = (float*)dsym(g_part);
    float* ghraw = (float*)dsym(g_Hraw);

    // conversions
    k_convX<<<dim3(64, 2), 256>>>(xt, xn);
    WPtrs wp;
    for (int i = 0; i < 4; i++) { wp.s[i] = W1[i]; wp.s[4 + i] = W2[i]; }
    wp.s[8] = fW1; wp.s[9] = fW2; wp.s[10] = thT; wp.s[11] = thN;
    k_convW<<<300, 256>>>(wp);

    MmaP p;

    // part1: P = X^T @ W1 per head, split-K 8 x 256
    memset(&p, 0, sizeof(p));
    for (int z = 0; z < 4; z++) {
        int sideA = (z == 0 || z == 3) ? 0 : 1;
        p.AH[z] = xth + (size_t)sideA * 262144; p.AL[z] = xtl + (size_t)sideA * 262144;
        p.BH[z] = w1h + (size_t)z * 262144;     p.BL[z] = w1l + (size_t)z * 262144;
        p.outF[z] = gp + (size_t)z * 131072;
    }
    p.ldA = 2048; p.ldB = 2048; p.Kchunk = 256; p.chunkStride = 16384; p.mode = 0;
    k_mma<<<dim3(1, 8, 4), 256, SMEM>>>(p);

    // Y = x @ theta -> YT (independent; mode2 transposed, ldO 2048)
    memset(&p, 0, sizeof(p));
    for (int z = 0; z < 2; z++) {
        p.AH[z] = xch + z * 128;    p.AL[z] = xcl + z * 128;
        p.BH[z] = thh + z * 16384;  p.BL[z] = thl + z * 16384;
        p.oH[z] = yth + (size_t)z * 262144; p.oL[z] = ytl + (size_t)z * 262144;
    }
    p.ldA = 256; p.ldB = 128; p.ldO = 2048; p.Kchunk = 128; p.mode = 2;
    k_mma<<<dim3(16, 1, 2), 256, SMEM>>>(p);

    k_redP1<<<dim3(64, 4), 256>>>(B1[0], B1[1], B1[2], B1[3]);

    // M = P1 @ W2 + b2 -> MA combined [side][128][256] (mode6 row-major bf16 + bias)
    memset(&p, 0, sizeof(p));
    for (int z = 0; z < 4; z++) {
        p.AH[z] = p1h + z * 16384; p.AL[z] = p1l + z * 16384;
        p.BH[z] = w2h + z * 16384; p.BL[z] = w2l + z * 16384;
        p.oH[z] = mah + (z & 1) * 32768 + ((z >> 1) << 7);
        p.oL[z] = mal + (z & 1) * 32768 + ((z >> 1) << 7);
        p.aux[z] = B2[z];
    }
    p.ldA = 128; p.ldB = 128; p.ldO = 256; p.Kchunk = 128; p.mode = 6;
    k_mma<<<dim3(1, 1, 4), 256, SMEM>>>(p);

    // G = MA @ BGT (K=256) -> GTC transposed combined [128][256]
    memset(&p, 0, sizeof(p));
    for (int z = 0; z < 2; z++) {
        p.AH[z] = mah + z * 32768; p.AL[z] = mal + z * 32768;
        p.BH[z] = bgh + z * 32768; p.BL[z] = bgl + z * 32768;
        p.oH[z] = gth + z * 128;   p.oL[z] = gtl + z * 128;
    }
    p.ldA = 256; p.ldB = 256; p.ldO = 256; p.Kchunk = 256; p.mode = 2;
    k_mma<<<dim3(1, 1, 2), 256, SMEM>>>(p);

    // Htmp = relu(XC @ GTC^T + fb1) (K=256, mode7 bf16 row-major)
    memset(&p, 0, sizeof(p));
    p.AH[0] = xch; p.AL[0] = xcl; p.BH[0] = gth; p.BL[0] = gtl;
    p.oH[0] = htmh; p.oL[0] = html; p.aux[0] = fb1;
    p.ldA = 256; p.ldB = 256; p.ldO = 128; p.Kchunk = 256; p.mode = 7;
    k_mma<<<dim3(16, 1, 1), 256, SMEM>>>(p);

    // f2: Hraw = Htmp @ fW2 + fb2 (mode4 fp32)
    memset(&p, 0, sizeof(p));
    p.AH[0] = htmh; p.AL[0] = html; p.BH[0] = f2h; p.BL[0] = f2l;
    p.outF[0] = ghraw; p.aux[0] = fb2;
    p.ldA = 128; p.ldB = 128; p.Kchunk = 128; p.mode = 4;
    k_mma<<<dim3(16, 1, 1), 256, SMEM>>>(p);

    k_colsm<<<128, 256>>>();
    k_convH<<<64, 256>>>();
    k_jsd<<<dim3(36, 8), 256>>>();
    k_w<<<1, 128>>>();

    // ZT[d,e] = sum_n Y[n,d] H[n,e]  (A=YT, B=HT), split-K 8 x 256
    memset(&p, 0, sizeof(p));
    for (int z = 0; z < 2; z++) {
        p.AH[z] = yth + (size_t)z * 262144; p.AL[z] = ytl + (size_t)z * 262144;
        p.BH[z] = hth;                      p.BL[z] = htl;
        p.outF[z] = gp + (size_t)z * 131072;
    }
    p.ldA = 2048; p.ldB = 2048; p.Kchunk = 256; p.chunkStride = 16384; p.mode = 0;
    k_mma<<<dim3(1, 8, 2), 256, SMEM>>>(p);

    k_redZW<<<dim3(64, 2), 256>>>();

    // final: out = x + elu(H @ Zw^T)
    memset(&p, 0, sizeof(p));
    for (int z = 0; z < 2; z++) {
        p.AH[z] = hh; p.AL[z] = hl;
        p.BH[z] = zwh + z * 16384; p.BL[z] = zwl + z * 16384;
        p.outF[z] = out + (size_t)z * 262144;
        p.aux[z] = z ? xn : xt;
    }
    p.ldA = 128; p.ldB = 128; p.Kchunk = 128; p.mode = 5;
    k_mma<<<dim3(16, 1, 2), 256, SMEM>>>(p);
}

// round 11
// speedup vs baseline: 1.6500x; 1.6500x over previous
#include <cuda_runtime.h>

// ---------------- problem constants ----------------
#define NTOT 2048      // N*T
#define JROWS 288      // 36 tiles * 8 n-chunks
#define EPSV 1e-6f

typedef unsigned long long u64;

// ---------------- scratch (device globals; no allocation) ----------------
static __device__ __align__(16) float g_part1[1048576];
static __device__ __align__(16) float g_P1  [4 * 128 * 128];
static __device__ __align__(16) float g_M   [4 * 128 * 128];
static __device__ __align__(16) float g_G   [2 * 128 * 128];
static __device__ __align__(16) float g_Htmp[NTOT * 128];
static __device__ __align__(16) float g_Hraw[NTOT * 128];
static __device__ __align__(16) float g_H   [NTOT * 128];
static __device__ __align__(16) float g_logH[NTOT * 128];
static __device__ __align__(16) float g_jpart[JROWS * 128];
static __device__ __align__(16) float g_w   [128];
static __device__ __align__(16) float g_Y   [2 * NTOT * 128];
static __device__ __align__(16) float g_partZ[2 * 32 * 128 * 128];
static __device__ __align__(16) float g_Zw  [2 * 128 * 128];

// ---------------- f32x2 helpers ----------------
__device__ __forceinline__ u64 pack_dup(float x) {
    u64 r; asm("mov.b64 %0, {%1, %1};" : "=l"(r) : "f"(x)); return r;
}
__device__ __forceinline__ void ffma2(u64& d, u64 a, u64 b) {
    asm("fma.rn.f32x2 %0, %1, %2, %0;" : "+l"(d) : "l"(a), "l"(b));
}
__device__ __forceinline__ float4 accrow(u64 a, u64 b) {
    float4 r;
    asm("mov.b64 {%0, %1}, %4;\n\tmov.b64 {%2, %3}, %5;"
        : "=f"(r.x), "=f"(r.y), "=f"(r.z), "=f"(r.w) : "l"(a), "l"(b));
    return r;
}

// ---------------- tile loaders (256 threads, BK=16, BN=128) ----------------
__device__ __forceinline__ void ldgB(const float* __restrict__ B, int ldb, int kRow,
                                     int tid, float4& r0, float4& r1) {
    int i0 = tid * 2, i1 = i0 + 1;
    r0 = *(const float4*)(B + (size_t)(kRow + (i0 >> 5)) * ldb + (i0 & 31) * 4);
    r1 = *(const float4*)(B + (size_t)(kRow + (i1 >> 5)) * ldb + (i1 & 31) * 4);
}
__device__ __forceinline__ void stsB(float* sB, int tid, float4 r0, float4 r1) {
    int i0 = tid * 2, i1 = i0 + 1;
    *(float4*)(sB + (i0 >> 5) * 128 + (i0 & 31) * 4) = r0;
    *(float4*)(sB + (i1 >> 5) * 128 + (i1 & 31) * 4) = r1;
}
// A tile for TN (A K-major [K x 128]); direct copy into sA [16][68]
__device__ __forceinline__ float4 ldgAt(const float* __restrict__ A, int mBase,
                                        int k0, int tid) {
    return *(const float4*)(A + (size_t)(k0 + (tid >> 4)) * 128 + mBase + (tid & 15) * 4);
}
__device__ __forceinline__ void stsAt(float* sA, int tid, float4 v) {
    *(float4*)(sA + (tid >> 4) * 68 + (tid & 15) * 4) = v;
}
// A tile for NN BM=32: sA transposed [16][36]; only tids < 128 participate
__device__ __forceinline__ float4 ldgA32(const float* __restrict__ A, int lda,
                                         int rowBase, int k0, int tid) {
    return *(const float4*)(A + (size_t)(rowBase + (tid >> 2)) * lda + k0 + (tid & 3) * 4);
}
__device__ __forceinline__ void stsA32(float* sA, int tid, float4 v) {
    int r = tid >> 2, kc = (tid & 3) * 4;
    sA[(kc + 0) * 36 + r] = v.x;
    sA[(kc + 1) * 36 + r] = v.y;
    sA[(kc + 2) * 36 + r] = v.z;
    sA[(kc + 3) * 36 + r] = v.w;
}

// ---------------- compute blocks ----------------
__device__ __forceinline__ void comp64(const float* sA, const float* sB,
                                       u64 (&acc)[4][4], int tx, int ty) {
#pragma unroll
    for (int k = 0; k < 16; k++) {
        float4 a4 = *(const float4*)(sA + k * 68 + ty * 4);
        ulonglong2 b0 = *(const ulonglong2*)(sB + k * 128 + tx * 4);
        ulonglong2 b1 = *(const ulonglong2*)(sB + k * 128 + 64 + tx * 4);
        u64 d0 = pack_dup(a4.x), d1 = pack_dup(a4.y), d2 = pack_dup(a4.z), d3 = pack_dup(a4.w);
        ffma2(acc[0][0], d0, b0.x); ffma2(acc[0][1], d0, b0.y);
        ffma2(acc[0][2], d0, b1.x); ffma2(acc[0][3], d0, b1.y);
        ffma2(acc[1][0], d1, b0.x); ffma2(acc[1][1], d1, b0.y);
        ffma2(acc[1][2], d1, b1.x); ffma2(acc[1][3], d1, b1.y);
        ffma2(acc[2][0], d2, b0.x); ffma2(acc[2][1], d2, b0.y);
        ffma2(acc[2][2], d2, b1.x); ffma2(acc[2][3], d2, b1.y);
        ffma2(acc[3][0], d3, b0.x); ffma2(acc[3][1], d3, b0.y);
        ffma2(acc[3][2], d3, b1.x); ffma2(acc[3][3], d3, b1.y);
    }
}
__device__ __forceinline__ void comp32(const float* sA, const float* sB,
                                       u64 (&acc)[2][4], int tx, int ty) {
#pragma unroll
    for (int k = 0; k < 16; k++) {
        float2 a2 = *(const float2*)(sA + k * 36 + ty * 2);
        ulonglong2 b0 = *(const ulonglong2*)(sB + k * 128 + tx * 4);
        ulonglong2 b1 = *(const ulonglong2*)(sB + k * 128 + 64 + tx * 4);
        u64 d0 = pack_dup(a2.x), d1 = pack_dup(a2.y);
        ffma2(acc[0][0], d0, b0.x); ffma2(acc[0][1], d0, b0.y);
        ffma2(acc[0][2], d0, b1.x); ffma2(acc[0][3], d0, b1.y);
        ffma2(acc[1][0], d1, b0.x); ffma2(acc[1][1], d1, b0.y);
        ffma2(acc[1][2], d1, b1.x); ffma2(acc[1][3], d1, b1.y);
    }
}

// ---------------- block reductions ----------------
template <int NW>
__device__ __forceinline__ float block_sum(float v) {
    __shared__ float sred[8];
    __syncthreads();
#pragma unroll
    for (int o = 16; o; o >>= 1) v += __shfl_xor_sync(0xffffffffu, v, o);
    if ((threadIdx.x & 31) == 0) sred[threadIdx.x >> 5] = v;
    __syncthreads();
    float t = 0.f;
#pragma unroll
    for (int k = 0; k < NW; k++) t += sred[k];
    return t;
}
template <int NW>
__device__ __forceinline__ float block_max(float v) {
    __shared__ float sred[8];
    __syncthreads();
#pragma unroll
    for (int o = 16; o; o >>= 1) v = fmaxf(v, __shfl_xor_sync(0xffffffffu, v, o));
    if ((threadIdx.x & 31) == 0) sred[threadIdx.x >> 5] = v;
    __syncthreads();
    float t = -3.4e38f;
#pragma unroll
    for (int k = 0; k < NW; k++) t = fmaxf(t, sred[k]);
    return t;
}

// ================= K1: split-K partials of P = X^T @ W1 (per head) =================
// grid (2 m-tiles, 16 chunks, 4 heads); K-chunk = 128
__global__ __launch_bounds__(256) void k_part1(
    const float* __restrict__ xt, const float* __restrict__ xn,
    const float* __restrict__ w_it, const float* __restrict__ w_inw,
    const float* __restrict__ w_t2n, const float* __restrict__ w_n2t)
{
    __shared__ __align__(16) float sA[16 * 68];
    __shared__ __align__(16) float sB[16 * 128];
    int head = blockIdx.z;
    const float* A = (head == 0 || head == 3) ? xt : xn;
    const float* B = (head == 0) ? w_it : (head == 1) ? w_inw : (head == 2) ? w_t2n : w_n2t;
    int mBase = blockIdx.x * 64;
    int kBeg = blockIdx.y * 128;
    int tid = threadIdx.x, tx = tid & 15, ty = tid >> 4;
    u64 acc[4][4] = {};
    float4 ra = ldgAt(A, mBase, kBeg, tid);
    float4 rb0, rb1; ldgB(B, 128, kBeg, tid, rb0, rb1);
    for (int s = 0; s < 8; s++) {
        __syncthreads();
        stsAt(sA, tid, ra); stsB(sB, tid, rb0, rb1);
        __syncthreads();
        if (s < 7) { ra = ldgAt(A, mBase, kBeg + (s + 1) * 16, tid); ldgB(B, 128, kBeg + (s + 1) * 16, tid, rb0, rb1); }
        comp64(sA, sB, acc, tx, ty);
    }
    float* C = g_part1 + (size_t)(head * 16 + blockIdx.y) * 16384;
    int r0 = mBase + ty * 4;
#pragma unroll
    for (int u = 0; u < 4; u++) {
        *(float4*)(C + (r0 + u) * 128 + tx * 4)      = accrow(acc[u][0], acc[u][1]);
        *(float4*)(C + (r0 + u) * 128 + 64 + tx * 4) = accrow(acc[u][2], acc[u][3]);
    }
}

// ================= K2: reduce 16 chunks + bias + relu -> P1 =================
__global__ __launch_bounds__(256) void k_red1(
    const float* __restrict__ b_it, const float* __restrict__ b_inw,
    const float* __restrict__ b_t2n, const float* __restrict__ b_n2t)
{
    int head = blockIdx.y;
    int i4 = blockIdx.x * 256 + threadIdx.x;   // < 4096 float4s per head
    const float* b = (head == 0) ? b_it : (head == 1) ? b_inw : (head == 2) ? b_t2n : b_n2t;
    float4 s = ((const float4*)b)[i4 & 31];
#pragma unroll
    for (int c = 0; c < 16; c++) {
        float4 p = ((const float4*)g_part1)[(size_t)(head * 16 + c) * 4096 + i4];
        s.x += p.x; s.y += p.y; s.z += p.z; s.w += p.w;
    }
    s.x = fmaxf(s.x, 0.f); s.y = fmaxf(s.y, 0.f); s.z = fmaxf(s.z, 0.f); s.w = fmaxf(s.w, 0.f);
    ((float4*)g_P1)[head * 4096 + i4] = s;
}

// ================= K3: M = P1 @ W2 + b2 (BM=32) =================
__global__ __launch_bounds__(256) void k_M(
    const float* __restrict__ w2_it, const float* __restrict__ w2_inw,
    const float* __restrict__ w2_t2n, const float* __restrict__ w2_n2t,
    const float* __restrict__ b2_it, const float* __restrict__ b2_inw,
    const float* __restrict__ b2_t2n, const float* __restrict__ b2_n2t)
{
    __shared__ __align__(16) float sA[16 * 36];
    __shared__ __align__(16) float sB[16 * 128];
    int head = blockIdx.z;
    const float* A = g_P1 + head * 16384;
    const float* B = (head == 0) ? w2_it : (head == 1) ? w2_inw : (head == 2) ? w2_t2n : w2_n2t;
    const float* bias = (head == 0) ? b2_it : (head == 1) ? b2_inw : (head == 2) ? b2_t2n : b2_n2t;
    int rowBase = blockIdx.x * 32;
    int tid = threadIdx.x, tx = tid & 15, ty = tid >> 4;
    u64 acc[2][4] = {};
    float4 ra; if (tid < 128) ra = ldgA32(A, 128, rowBase, 0, tid);
    float4 rb0, rb1; ldgB(B, 128, 0, tid, rb0, rb1);
    for (int s = 0; s < 8; s++) {
        __syncthreads();
        if (tid < 128) stsA32(sA, tid, ra);
        stsB(sB, tid, rb0, rb1);
        __syncthreads();
        if (s < 7) { if (tid < 128) ra = ldgA32(A, 128, rowBase, (s + 1) * 16, tid); ldgB(B, 128, (s + 1) * 16, tid, rb0, rb1); }
        comp32(sA, sB, acc, tx, ty);
    }
    float* C = g_M + head * 16384;
    float4 bb0 = *(const float4*)(bias + tx * 4);
    float4 bb1 = *(const float4*)(bias + 64 + tx * 4);
    int r0 = rowBase + ty * 2;
#pragma unroll
    for (int u = 0; u < 2; u++) {
        float4 v0 = accrow(acc[u][0], acc[u][1]);
        float4 v1 = accrow(acc[u][2], acc[u][3]);
        v0.x += bb0.x; v0.y += bb0.y; v0.z += bb0.z; v0.w += bb0.w;
        v1.x += bb1.x; v1.y += bb1.y; v1.z += bb1.z; v1.w += bb1.w;
        *(float4*)(C + (r0 + u) * 128 + tx * 4) = v0;
        *(float4*)(C + (r0 + u) * 128 + 64 + tx * 4) = v1;
    }
}

// ================= K4: G_side = sum over 2 heads M_h @ F_h  (BM=32) =================
// side 0 (xt): heads {0,2};  side 1 (xn): heads {1,3}.  F_h = fW1[h*128:(h+1)*128, :]
__global__ __launch_bounds__(256) void k_G(const float* __restrict__ fW1)
{
    __shared__ __align__(16) float sA[16 * 36];
    __shared__ __align__(16) float sB[16 * 128];
    int side = blockIdx.z;
    int rowBase = blockIdx.x * 32;
    int tid = threadIdx.x, tx = tid & 15, ty = tid >> 4;
    u64 acc[2][4] = {};
#pragma unroll
    for (int pass = 0; pass < 2; pass++) {
        int head = side + pass * 2;
        const float* A = g_M + head * 16384;
        const float* B = fW1 + head * 128 * 128;
        float4 ra; if (tid < 128) ra = ldgA32(A, 128, rowBase, 0, tid);
        float4 rb0, rb1; ldgB(B, 128, 0, tid, rb0, rb1);
        for (int s = 0; s < 8; s++) {
            __syncthreads();
            if (tid < 128) stsA32(sA, tid, ra);
            stsB(sB, tid, rb0, rb1);
            __syncthreads();
            if (s < 7) { if (tid < 128) ra = ldgA32(A, 128, rowBase, (s + 1) * 16, tid); ldgB(B, 128, (s + 1) * 16, tid, rb0, rb1); }
            comp32(sA, sB, acc, tx, ty);
        }
        __syncthreads();
    }
    float* C = g_G + side * 16384;
    int r0 = rowBase + ty * 2;
#pragma unroll
    for (int u = 0; u < 2; u++) {
        *(float4*)(C + (r0 + u) * 128 + tx * 4)      = accrow(acc[u][0], acc[u][1]);
        *(float4*)(C + (r0 + u) * 128 + 64 + tx * 4) = accrow(acc[u][2], acc[u][3]);
    }
}

// ================= K5: Htmp = relu(xt@G0 + xn@G1 + fb1) (BM=32) =================
__global__ __launch_bounds__(256) void k_Htmp(
    const float* __restrict__ xt, const float* __restrict__ xn,
    const float* __restrict__ fb1)
{
    __shared__ __align__(16) float sA[16 * 36];
    __shared__ __align__(16) float sB[16 * 128];
    int rowBase = blockIdx.x * 32;
    int tid = threadIdx.x, tx = tid & 15, ty = tid >> 4;
    u64 acc[2][4] = {};
#pragma unroll
    for (int pass = 0; pass < 2; pass++) {
        const float* A = pass ? xn : xt;
        const float* B = g_G + pass * 16384;
        float4 ra; if (tid < 128) ra = ldgA32(A, 128, rowBase, 0, tid);
        float4 rb0, rb1; ldgB(B, 128, 0, tid, rb0, rb1);
        for (int s = 0; s < 8; s++) {
            __syncthreads();
            if (tid < 128) stsA32(sA, tid, ra);
            stsB(sB, tid, rb0, rb1);
            __syncthreads();
            if (s < 7) { if (tid < 128) ra = ldgA32(A, 128, rowBase, (s + 1) * 16, tid); ldgB(B, 128, (s + 1) * 16, tid, rb0, rb1); }
            comp32(sA, sB, acc, tx, ty);
        }
        __syncthreads();
    }
    float4 bb0 = *(const float4*)(fb1 + tx * 4);
    float4 bb1 = *(const float4*)(fb1 + 64 + tx * 4);
    int r0 = rowBase + ty * 2;
#pragma unroll
    for (int u = 0; u < 2; u++) {
        float4 v0 = accrow(acc[u][0], acc[u][1]);
        float4 v1 = accrow(acc[u][2], acc[u][3]);
        v0.x = fmaxf(v0.x + bb0.x, 0.f); v0.y = fmaxf(v0.y + bb0.y, 0.f);
        v0.z = fmaxf(v0.z + bb0.z, 0.f); v0.w = fmaxf(v0.w + bb0.w, 0.f);
        v1.x = fmaxf(v1.x + bb1.x, 0.f); v1.y = fmaxf(v1.y + bb1.y, 0.f);
        v1.z = fmaxf(v1.z + bb1.z, 0.f); v1.w = fmaxf(v1.w + bb1.w, 0.f);
        *(float4*)(g_Htmp + (size_t)(r0 + u) * 128 + tx * 4) = v0;
        *(float4*)(g_Htmp + (size_t)(r0 + u) * 128 + 64 + tx * 4) = v1;
    }
}

// ================= K6: Hraw = Htmp @ f_W2 + f_b2 (BM=32) =================
__global__ __launch_bounds__(256) void k_f2(
    const float* __restrict__ fW2, const float* __restrict__ fb2)
{
    __shared__ __align__(16) float sA[16 * 36];
    __shared__ __align__(16) float sB[16 * 128];
    int rowBase = blockIdx.x * 32;
    int tid = threadIdx.x, tx = tid & 15, ty = tid >> 4;
    u64 acc[2][4] = {};
    float4 ra; if (tid < 128) ra = ldgA32(g_Htmp, 128, rowBase, 0, tid);
    float4 rb0, rb1; ldgB(fW2, 128, 0, tid, rb0, rb1);
    for (int s = 0; s < 8; s++) {
        __syncthreads();
        if (tid < 128) stsA32(sA, tid, ra);
        stsB(sB, tid, rb0, rb1);
        __syncthreads();
        if (s < 7) { if (tid < 128) ra = ldgA32(g_Htmp, 128, rowBase, (s + 1) * 16, tid); ldgB(fW2, 128, (s + 1) * 16, tid, rb0, rb1); }
        comp32(sA, sB, acc, tx, ty);
    }
    float4 bb0 = *(const float4*)(fb2 + tx * 4);
    float4 bb1 = *(const float4*)(fb2 + 64 + tx * 4);
    int r0 = rowBase + ty * 2;
#pragma unroll
    for (int u = 0; u < 2; u++) {
        float4 v0 = accrow(acc[u][0], acc[u][1]);
        float4 v1 = accrow(acc[u][2], acc[u][3]);
        v0.x += bb0.x; v0.y += bb0.y; v0.z += bb0.z; v0.w += bb0.w;
        v1.x += bb1.x; v1.y += bb1.y; v1.z += bb1.z; v1.w += bb1.w;
        *(float4*)(g_Hraw + (size_t)(r0 + u) * 128 + tx * 4) = v0;
        *(float4*)(g_Hraw + (size_t)(r0 + u) * 128 + 64 + tx * 4) = v1;
    }
}

// ================= K7: per-column standardize + softmax -> H, logH =================
__global__ __launch_bounds__(256) void k_colsm()
{
    int e = blockIdx.x;
    __shared__ float s[NTOT];
    int tid = threadIdx.x;
    for (int n = tid; n < NTOT; n += 256) s[n] = g_Hraw[n * 128 + e];
    __syncthreads();

    float lsum = 0.f;
    for (int n = tid; n < NTOT; n += 256) lsum += s[n];
    float mean = block_sum<8>(lsum) * (1.f / NTOT);

    float lss = 0.f;
    for (int n = tid; n < NTOT; n += 256) { float d = s[n] - mean; lss += d * d; }
    float var = block_sum<8>(lss) * (1.f / (NTOT - 1));
    float inv = 1.f / (sqrtf(var) + EPSV);

    float lmax = -3.4e38f;
    for (int n = tid; n < NTOT; n += 256) {
        float z = (s[n] - mean) * inv;
        s[n] = z;
        lmax = fmaxf(lmax, z);
    }
    __syncthreads();
    float mx = block_max<8>(lmax);

    float lse = 0.f;
    for (int n = tid; n < NTOT; n += 256) lse += __expf(s[n] - mx);
    float sum = block_sum<8>(lse);
    float invs = 1.f / sum;
    float lls = __logf(sum);

    for (int n = tid; n < NTOT; n += 256) {
        float z = s[n];
        g_H[n * 128 + e]    = __expf(z - mx) * invs;
        g_logH[n * 128 + e] = (z - mx) - lls;
    }
}

// ================= K8: pairwise JSD -> per-column partial sums =================
__global__ __launch_bounds__(256) void k_jsd()
{
    int t = blockIdx.x;
    int bi = 0, rem = t;
    while (rem >= 8 - bi) { rem -= 8 - bi; bi++; }
    int bj = bi + rem;
    int tid = threadIdx.x;
    int ti = tid & 15, tj = tid >> 4;
    int i = bi * 16 + ti, j = bj * 16 + tj;

    __shared__ float sHi[16][16], sLi[16][16], sHj[16][16], sLj[16][16];
    float acci = 0.f, accj = 0.f;
    int lr = tid >> 4, lc = tid & 15;
    int nBeg = blockIdx.y * 256;

    for (int n0 = nBeg; n0 < nBeg + 256; n0 += 16) {
        __syncthreads();
        int n = n0 + lr;
        sHi[lr][lc] = g_H   [n * 128 + bi * 16 + lc];
        sLi[lr][lc] = g_logH[n * 128 + bi * 16 + lc];
        sHj[lr][lc] = g_H   [n * 128 + bj * 16 + lc];
        sLj[lr][lc] = g_logH[n * 128 + bj * 16 + lc];
        __syncthreads();
#pragma unroll
        for (int r = 0; r < 16; r++) {
            float hi = sHi[r][ti], hj = sHj[r][tj];
            float m  = 0.5f * (hi + hj);
            float lm = __logf(m);
            acci += hi * (sLi[r][ti] - lm);
            accj += hj * (sLj[r][tj] - lm);
        }
    }
    float v = (i < j) ? 0.5f * (acci + accj) : 0.f;

    __shared__ float red[16][16];
    __syncthreads();
    red[tj][ti] = v;
    __syncthreads();

    float* out = g_jpart + (size_t)(blockIdx.y * 36 + blockIdx.x) * 128;
    if (tid < 128) out[tid] = 0.f;
    __syncthreads();
    if (tid < 16) {
        float si = 0.f, sj = 0.f;
#pragma unroll
        for (int r = 0; r < 16; r++) { si += red[r][tid]; sj += red[tid][r]; }
        out[bi * 16 + tid] += si;
        out[bj * 16 + tid] += sj;
    }
}

// ================= K9: jm -> standardized -> softmax -> w =================
__global__ __launch_bounds__(128) void k_w()
{
    int e = threadIdx.x;
    float cs = 0.f;
    for (int r = 0; r < JROWS; r++) cs += g_jpart[r * 128 + e];
    float jm = cs * (1.f / 128.f);

    float mean = block_sum<4>(jm) * (1.f / 128.f);
    float d = jm - mean;
    float var = block_sum<4>(d * d) * (1.f / 127.f);
    float njm = d / (sqrtf(var) + EPSV);

    float mx = block_max<4>(njm);
    float ex = __expf(njm - mx);
    float sum = block_sum<4>(ex);
    g_w[e] = ex / sum;
}

// ================= K10: Y = x @ theta (BM=32) =================
__global__ __launch_bounds__(256) void k_Y(
    const float* __restrict__ xt, const float* __restrict__ xn,
    const float* __restrict__ th_t, const float* __restrict__ th_n)
{
    __shared__ __align__(16) float sA[16 * 36];
    __shared__ __align__(16) float sB[16 * 128];
    int side = blockIdx.z;
    const float* A = side ? xn : xt;
    const float* B = side ? th_n : th_t;
    int rowBase = blockIdx.x * 32;
    int tid = threadIdx.x, tx = tid & 15, ty = tid >> 4;
    u64 acc[2][4] = {};
    float4 ra; if (tid < 128) ra = ldgA32(A, 128, rowBase, 0, tid);
    float4 rb0, rb1; ldgB(B, 128, 0, tid, rb0, rb1);
    for (int s = 0; s < 8; s++) {
        __syncthreads();
        if (tid < 128) stsA32(sA, tid, ra);
        stsB(sB, tid, rb0, rb1);
        __syncthreads();
        if (s < 7) { if (tid < 128) ra = ldgA32(A, 128, rowBase, (s + 1) * 16, tid); ldgB(B, 128, (s + 1) * 16, tid, rb0, rb1); }
        comp32(sA, sB, acc, tx, ty);
    }
    float* C = g_Y + (size_t)side * NTOT * 128;
    int r0 = rowBase + ty * 2;
#pragma unroll
    for (int u = 0; u < 2; u++) {
        *(float4*)(C + (size_t)(r0 + u) * 128 + tx * 4)      = accrow(acc[u][0], acc[u][1]);
        *(float4*)(C + (size_t)(r0 + u) * 128 + 64 + tx * 4) = accrow(acc[u][2], acc[u][3]);
    }
}

// ================= K11: split-K partials of Z = H^T @ Y (BM=64) =================
// grid (2 m-tiles, 32 chunks, 2 sides); K-chunk = 64
__global__ __launch_bounds__(256) void k_partZ()
{
    __shared__ __align__(16) float sA[16 * 68];
    __shared__ __align__(16) float sB[16 * 128];
    int side = blockIdx.z;
    const float* B = g_Y + (size_t)side * NTOT * 128;
    int mBase = blockIdx.x * 64;
    int kBeg = blockIdx.y * 64;
    int tid = threadIdx.x, tx = tid & 15, ty = tid >> 4;
    u64 acc[4][4] = {};
    float4 ra = ldgAt(g_H, mBase, kBeg, tid);
    float4 rb0, rb1; ldgB(B, 128, kBeg, tid, rb0, rb1);
    for (int s = 0; s < 4; s++) {
        __syncthreads();
        stsAt(sA, tid, ra); stsB(sB, tid, rb0, rb1);
        __syncthreads();
        if (s < 3) { ra = ldgAt(g_H, mBase, kBeg + (s + 1) * 16, tid); ldgB(B, 128, kBeg + (s + 1) * 16, tid, rb0, rb1); }
        comp64(sA, sB, acc, tx, ty);
    }
    float* C = g_partZ + (size_t)(side * 32 + blockIdx.y) * 16384;
    int r0 = mBase + ty * 4;
#pragma unroll
    for (int u = 0; u < 4; u++) {
        *(float4*)(C + (r0 + u) * 128 + tx * 4)      = accrow(acc[u][0], acc[u][1]);
        *(float4*)(C + (r0 + u) * 128 + 64 + tx * 4) = accrow(acc[u][2], acc[u][3]);
    }
}

// ================= K12: Zw = w * (sum chunks) =================
__global__ __launch_bounds__(256) void k_redZ()
{
    int side = blockIdx.y;
    int i4 = blockIdx.x * 256 + threadIdx.x;   // < 4096
    float4 s = make_float4(0.f, 0.f, 0.f, 0.f);
#pragma unroll
    for (int c = 0; c < 32; c++) {
        float4 p = ((const float4*)g_partZ)[(size_t)(side * 32 + c) * 4096 + i4];
        s.x += p.x; s.y += p.y; s.z += p.z; s.w += p.w;
    }
    float wv = g_w[i4 >> 5];
    s.x *= wv; s.y *= wv; s.z *= wv; s.w *= wv;
    ((float4*)g_Zw)[side * 4096 + i4] = s;
}

// ================= K13: out = x + elu(H @ Zw) (BM=32) =================
__global__ __launch_bounds__(256) void k_final(
    const float* __restrict__ xt, const float* __restrict__ xn,
    float* __restrict__ out)
{
    __shared__ __align__(16) float sA[16 * 36];
    __shared__ __align__(16) float sB[16 * 128];
    int side = blockIdx.z;
    const float* x = side ? xn : xt;
    const float* B = g_Zw + side * 16384;
    int rowBase = blockIdx.x * 32;
    int tid = threadIdx.x, tx = tid & 15, ty = tid >> 4;
    u64 acc[2][4] = {};
    float4 ra; if (tid < 128) ra = ldgA32(g_H, 128, rowBase, 0, tid);
    float4 rb0, rb1; ldgB(B, 128, 0, tid, rb0, rb1);
    for (int s = 0; s < 8; s++) {
        __syncthreads();
        if (tid < 128) stsA32(sA, tid, ra);
        stsB(sB, tid, rb0, rb1);
        __syncthreads();
        if (s < 7) { if (tid < 128) ra = ldgA32(g_H, 128, rowBase, (s + 1) * 16, tid); ldgB(B, 128, (s + 1) * 16, tid, rb0, rb1); }
        comp32(sA, sB, acc, tx, ty);
    }
    float* o = out + (size_t)side * NTOT * 128;
    int r0 = rowBase + ty * 2;
#pragma unroll
    for (int u = 0; u < 2; u++) {
#pragma unroll
        for (int h = 0; h < 2; h++) {
            float4 v = accrow(acc[u][h * 2], acc[u][h * 2 + 1]);
            int c = h * 64 + tx * 4;
            float4 xv = *(const float4*)(x + (size_t)(r0 + u) * 128 + c);
            v.x = xv.x + ((v.x > 0.f) ? v.x : expm1f(v.x));
            v.y = xv.y + ((v.y > 0.f) ? v.y : expm1f(v.y));
            v.z = xv.z + ((v.z > 0.f) ? v.z : expm1f(v.z));
            v.w = xv.w + ((v.w > 0.f) ? v.w : expm1f(v.w));
            *(float4*)(o + (size_t)(r0 + u) * 128 + c) = v;
        }
    }
}

// ---------------- launch ----------------
extern "C" void kernel_launch(void* const* d_in, const int* in_sizes, int n_in,
                              void* d_out, int out_size)
{
    const float* xt    = (const float*)d_in[0];
    const float* xn    = (const float*)d_in[1];
    const float* itW1  = (const float*)d_in[2];
    const float* itb1  = (const float*)d_in[3];
    const float* itW2  = (const float*)d_in[4];
    const float* itb2  = (const float*)d_in[5];
    const float* inwW1 = (const float*)d_in[6];
    const float* inwb1 = (const float*)d_in[7];
    const float* inwW2 = (const float*)d_in[8];
    const float* inwb2 = (const float*)d_in[9];
    const float* t2nW1 = (const float*)d_in[10];
    const float* t2nb1 = (const float*)d_in[11];
    const float* t2nW2 = (const float*)d_in[12];
    const float* t2nb2 = (const float*)d_in[13];
    const float* n2tW1 = (const float*)d_in[14];
    const float* n2tb1 = (const float*)d_in[15];
    const float* n2tW2 = (const float*)d_in[16];
    const float* n2tb2 = (const float*)d_in[17];
    const float* fW1   = (const float*)d_in[18];
    const float* fb1   = (const float*)d_in[19];
    const float* fW2   = (const float*)d_in[20];
    const float* fb2   = (const float*)d_in[21];
    const float* thT   = (const float*)d_in[22];
    const float* thN   = (const float*)d_in[23];
    float* out = (float*)d_out;

    k_part1<<<dim3(2, 16, 4), 256>>>(xt, xn, itW1, inwW1, t2nW1, n2tW1);
    k_red1 <<<dim3(16, 4), 256>>>(itb1, inwb1, t2nb1, n2tb1);
    k_M    <<<dim3(4, 1, 4), 256>>>(itW2, inwW2, t2nW2, n2tW2, itb2, inwb2, t2nb2, n2tb2);
    k_G    <<<dim3(4, 1, 2), 256>>>(fW1);
    k_Htmp <<<64, 256>>>(xt, xn, fb1);
    k_f2   <<<64, 256>>>(fW2, fb2);
    k_colsm<<<128, 256>>>();
    k_jsd  <<<dim3(36, 8), 256>>>();
    k_w    <<<1, 128>>>();
    k_Y    <<<dim3(64, 1, 2), 256>>>(xt, xn, thT, thN);
    k_partZ<<<dim3(2, 32, 2), 256>>>();
    k_redZ <<<dim3(16, 2), 256>>>();
    k_final<<<dim3(64, 1, 2), 256>>>(xt, xn, out);
}

// round 12
// speedup vs baseline: 1.9504x; 1.1821x over previous
#include <cuda_runtime.h>

// ---------------- problem constants ----------------
#define NTOT 2048      // N*T
#define JROWS 288      // 36 tiles * 8 n-chunks
#define EPSV 1e-6f

typedef unsigned long long u64;

// ---------------- scratch (device globals; no allocation) ----------------
static __device__ __align__(16) float g_part1[1048576];
static __device__ __align__(16) float g_P1  [4 * 128 * 128];
static __device__ __align__(16) float g_WF  [4 * 128 * 128];
static __device__ __align__(16) float g_bb  [256];
static __device__ __align__(16) float g_G   [2 * 128 * 128];
static __device__ __align__(16) float g_Htmp[NTOT * 128];
static __device__ __align__(16) float g_Hraw[NTOT * 128];
static __device__ __align__(16) float g_H   [NTOT * 128];
static __device__ __align__(16) float g_logH[NTOT * 128];
static __device__ __align__(16) float g_jpart[JROWS * 128];
static __device__ __align__(16) float g_w   [128];
static __device__ __align__(16) float g_Y   [2 * NTOT * 128];
static __device__ __align__(16) float g_partZ[2 * 32 * 128 * 128];
static __device__ __align__(16) float g_Zw  [2 * 128 * 128];

// ---------------- f32x2 helpers ----------------
__device__ __forceinline__ u64 pack_dup(float x) {
    u64 r; asm("mov.b64 %0, {%1, %1};" : "=l"(r) : "f"(x)); return r;
}
__device__ __forceinline__ void ffma2(u64& d, u64 a, u64 b) {
    asm("fma.rn.f32x2 %0, %1, %2, %0;" : "+l"(d) : "l"(a), "l"(b));
}
__device__ __forceinline__ float4 accrow(u64 a, u64 b) {
    float4 r;
    asm("mov.b64 {%0, %1}, %4;\n\tmov.b64 {%2, %3}, %5;"
        : "=f"(r.x), "=f"(r.y), "=f"(r.z), "=f"(r.w) : "l"(a), "l"(b));
    return r;
}

// ---------------- tile loaders (256 threads, BK=16, BN=128) ----------------
__device__ __forceinline__ void ldgB(const float* __restrict__ B, int ldb, int kRow,
                                     int tid, float4& r0, float4& r1) {
    int i0 = tid * 2, i1 = i0 + 1;
    r0 = *(const float4*)(B + (size_t)(kRow + (i0 >> 5)) * ldb + (i0 & 31) * 4);
    r1 = *(const float4*)(B + (size_t)(kRow + (i1 >> 5)) * ldb + (i1 & 31) * 4);
}
__device__ __forceinline__ void stsB(float* sB, int tid, float4 r0, float4 r1) {
    int i0 = tid * 2, i1 = i0 + 1;
    *(float4*)(sB + (i0 >> 5) * 128 + (i0 & 31) * 4) = r0;
    *(float4*)(sB + (i1 >> 5) * 128 + (i1 & 31) * 4) = r1;
}
// A tile for TN (A K-major [K x 128]); direct copy into sA [16][68]
__device__ __forceinline__ float4 ldgAt(const float* __restrict__ A, int mBase,
                                        int k0, int tid) {
    return *(const float4*)(A + (size_t)(k0 + (tid >> 4)) * 128 + mBase + (tid & 15) * 4);
}
__device__ __forceinline__ void stsAt(float* sA, int tid, float4 v) {
    *(float4*)(sA + (tid >> 4) * 68 + (tid & 15) * 4) = v;
}
// A tile NN BM=64: sA transposed [16][68]
__device__ __forceinline__ float4 ldgA64(const float* __restrict__ A, int lda,
                                         int rowBase, int k0, int tid) {
    return *(const float4*)(A + (size_t)(rowBase + (tid >> 2)) * lda + k0 + (tid & 3) * 4);
}
__device__ __forceinline__ void stsA64(float* sA, int tid, float4 v) {
    int r = tid >> 2, kc = (tid & 3) * 4;
    sA[(kc + 0) * 68 + r] = v.x;
    sA[(kc + 1) * 68 + r] = v.y;
    sA[(kc + 2) * 68 + r] = v.z;
    sA[(kc + 3) * 68 + r] = v.w;
}
// A tile NN BM=32: sA transposed [16][36]; only tids < 128 participate
__device__ __forceinline__ float4 ldgA32(const float* __restrict__ A, int lda,
                                         int rowBase, int k0, int tid) {
    return *(const float4*)(A + (size_t)(rowBase + (tid >> 2)) * lda + k0 + (tid & 3) * 4);
}
__device__ __forceinline__ void stsA32(float* sA, int tid, float4 v) {
    int r = tid >> 2, kc = (tid & 3) * 4;
    sA[(kc + 0) * 36 + r] = v.x;
    sA[(kc + 1) * 36 + r] = v.y;
    sA[(kc + 2) * 36 + r] = v.z;
    sA[(kc + 3) * 36 + r] = v.w;
}

// ---------------- compute blocks ----------------
__device__ __forceinline__ void comp64(const float* sA, const float* sB,
                                       u64 (&acc)[4][4], int tx, int ty) {
#pragma unroll
    for (int k = 0; k < 16; k++) {
        float4 a4 = *(const float4*)(sA + k * 68 + ty * 4);
        ulonglong2 b0 = *(const ulonglong2*)(sB + k * 128 + tx * 4);
        ulonglong2 b1 = *(const ulonglong2*)(sB + k * 128 + 64 + tx * 4);
        u64 d0 = pack_dup(a4.x), d1 = pack_dup(a4.y), d2 = pack_dup(a4.z), d3 = pack_dup(a4.w);
        ffma2(acc[0][0], d0, b0.x); ffma2(acc[0][1], d0, b0.y);
        ffma2(acc[0][2], d0, b1.x); ffma2(acc[0][3], d0, b1.y);
        ffma2(acc[1][0], d1, b0.x); ffma2(acc[1][1], d1, b0.y);
        ffma2(acc[1][2], d1, b1.x); ffma2(acc[1][3], d1, b1.y);
        ffma2(acc[2][0], d2, b0.x); ffma2(acc[2][1], d2, b0.y);
        ffma2(acc[2][2], d2, b1.x); ffma2(acc[2][3], d2, b1.y);
        ffma2(acc[3][0], d3, b0.x); ffma2(acc[3][1], d3, b0.y);
        ffma2(acc[3][2], d3, b1.x); ffma2(acc[3][3], d3, b1.y);
    }
}
__device__ __forceinline__ void comp32(const float* sA, const float* sB,
                                       u64 (&acc)[2][4], int tx, int ty) {
#pragma unroll
    for (int k = 0; k < 16; k++) {
        float2 a2 = *(const float2*)(sA + k * 36 + ty * 2);
        ulonglong2 b0 = *(const ulonglong2*)(sB + k * 128 + tx * 4);
        ulonglong2 b1 = *(const ulonglong2*)(sB + k * 128 + 64 + tx * 4);
        u64 d0 = pack_dup(a2.x), d1 = pack_dup(a2.y);
        ffma2(acc[0][0], d0, b0.x); ffma2(acc[0][1], d0, b0.y);
        ffma2(acc[0][2], d0, b1.x); ffma2(acc[0][3], d0, b1.y);
        ffma2(acc[1][0], d1, b0.x); ffma2(acc[1][1], d1, b0.y);
        ffma2(acc[1][2], d1, b1.x); ffma2(acc[1][3], d1, b1.y);
    }
}

// ---------------- block reductions ----------------
template <int NW>
__device__ __forceinline__ float block_sum(float v) {
    __shared__ float sred[8];
    __syncthreads();
#pragma unroll
    for (int o = 16; o; o >>= 1) v += __shfl_xor_sync(0xffffffffu, v, o);
    if ((threadIdx.x & 31) == 0) sred[threadIdx.x >> 5] = v;
    __syncthreads();
    float t = 0.f;
#pragma unroll
    for (int k = 0; k < NW; k++) t += sred[k];
    return t;
}
template <int NW>
__device__ __forceinline__ float block_max(float v) {
    __shared__ float sred[8];
    __syncthreads();
#pragma unroll
    for (int o = 16; o; o >>= 1) v = fmaxf(v, __shfl_xor_sync(0xffffffffu, v, o));
    if ((threadIdx.x & 31) == 0) sred[threadIdx.x >> 5] = v;
    __syncthreads();
    float t = -3.4e38f;
#pragma unroll
    for (int k = 0; k < NW; k++) t = fmaxf(t, sred[k]);
    return t;
}

// ================= stageA: part1(128) + Y(64) + WF(16) + bb(1) in ONE launch =================
__global__ __launch_bounds__(256) void k_stageA(
    const float* __restrict__ xt, const float* __restrict__ xn,
    const float* __restrict__ w_it, const float* __restrict__ w_inw,
    const float* __restrict__ w_t2n, const float* __restrict__ w_n2t,
    const float* __restrict__ th_t, const float* __restrict__ th_n,
    const float* __restrict__ w2_it, const float* __restrict__ w2_inw,
    const float* __restrict__ w2_t2n, const float* __restrict__ w2_n2t,
    const float* __restrict__ fW1,
    const float* __restrict__ b2_it, const float* __restrict__ b2_inw,
    const float* __restrict__ b2_t2n, const float* __restrict__ b2_n2t)
{
    __shared__ __align__(16) float sA[16 * 68];
    __shared__ __align__(16) float sB[16 * 128];
    int tid = threadIdx.x, tx = tid & 15, ty = tid >> 4;
    int bx = blockIdx.x;

    if (bx < 128) {
        // ---- part1: split-K partials of P = X^T @ W1 ----
        int head = bx >> 5, r = bx & 31;
        int mBase = (r & 1) * 64;
        int kBeg = (r >> 1) * 128;
        const float* A = (head == 0 || head == 3) ? xt : xn;
        const float* B = (head == 0) ? w_it : (head == 1) ? w_inw : (head == 2) ? w_t2n : w_n2t;
        u64 acc[4][4] = {};
        float4 ra = ldgAt(A, mBase, kBeg, tid);
        float4 rb0, rb1; ldgB(B, 128, kBeg, tid, rb0, rb1);
        for (int s = 0; s < 8; s++) {
            __syncthreads();
            stsAt(sA, tid, ra); stsB(sB, tid, rb0, rb1);
            __syncthreads();
            if (s < 7) { ra = ldgAt(A, mBase, kBeg + (s + 1) * 16, tid); ldgB(B, 128, kBeg + (s + 1) * 16, tid, rb0, rb1); }
            comp64(sA, sB, acc, tx, ty);
        }
        float* C = g_part1 + (size_t)(head * 16 + (r >> 1)) * 16384;
        int r0 = mBase + ty * 4;
#pragma unroll
        for (int u = 0; u < 4; u++) {
            *(float4*)(C + (r0 + u) * 128 + tx * 4)      = accrow(acc[u][0], acc[u][1]);
            *(float4*)(C + (r0 + u) * 128 + 64 + tx * 4) = accrow(acc[u][2], acc[u][3]);
        }
    } else if (bx < 192) {
        // ---- Y = x @ theta (BM=64 NN) ----
        int idx = bx - 128;
        int side = idx >> 5;
        int rowBase = (idx & 31) * 64;
        const float* A = side ? xn : xt;
        const float* B = side ? th_n : th_t;
        u64 acc[4][4] = {};
        float4 ra = ldgA64(A, 128, rowBase, 0, tid);
        float4 rb0, rb1; ldgB(B, 128, 0, tid, rb0, rb1);
        for (int s = 0; s < 8; s++) {
            __syncthreads();
            stsA64(sA, tid, ra); stsB(sB, tid, rb0, rb1);
            __syncthreads();
            if (s < 7) { ra = ldgA64(A, 128, rowBase, (s + 1) * 16, tid); ldgB(B, 128, (s + 1) * 16, tid, rb0, rb1); }
            comp64(sA, sB, acc, tx, ty);
        }
        float* C = g_Y + (size_t)side * NTOT * 128;
        int r0 = rowBase + ty * 4;
#pragma unroll
        for (int u = 0; u < 4; u++) {
            *(float4*)(C + (size_t)(r0 + u) * 128 + tx * 4)      = accrow(acc[u][0], acc[u][1]);
            *(float4*)(C + (size_t)(r0 + u) * 128 + 64 + tx * 4) = accrow(acc[u][2], acc[u][3]);
        }
    } else if (bx < 208) {
        // ---- WF_h = W2_h @ F_h (BM=32 NN) ----
        int idx = bx - 192;
        int head = idx >> 2;
        int rowBase = (idx & 3) * 32;
        const float* A = (head == 0) ? w2_it : (head == 1) ? w2_inw : (head == 2) ? w2_t2n : w2_n2t;
        const float* B = fW1 + head * 128 * 128;
        u64 acc[2][4] = {};
        float4 ra; if (tid < 128) ra = ldgA32(A, 128, rowBase, 0, tid);
        float4 rb0, rb1; ldgB(B, 128, 0, tid, rb0, rb1);
        for (int s = 0; s < 8; s++) {
            __syncthreads();
            if (tid < 128) stsA32(sA, tid, ra);
            stsB(sB, tid, rb0, rb1);
            __syncthreads();
            if (s < 7) { if (tid < 128) ra = ldgA32(A, 128, rowBase, (s + 1) * 16, tid); ldgB(B, 128, (s + 1) * 16, tid, rb0, rb1); }
            comp32(sA, sB, acc, tx, ty);
        }
        float* C = g_WF + head * 16384;
        int r0 = rowBase + ty * 2;
#pragma unroll
        for (int u = 0; u < 2; u++) {
            *(float4*)(C + (r0 + u) * 128 + tx * 4)      = accrow(acc[u][0], acc[u][1]);
            *(float4*)(C + (r0 + u) * 128 + 64 + tx * 4) = accrow(acc[u][2], acc[u][3]);
        }
    } else {
        // ---- bb[side][e] = sum_{h in side} b2_h @ F_h ----
        int side = tid >> 7, e = tid & 127;
        float s = 0.f;
#pragma unroll
        for (int p = 0; p < 2; p++) {
            int h = side + p * 2;
            const float* b2 = (h == 0) ? b2_it : (h == 1) ? b2_inw : (h == 2) ? b2_t2n : b2_n2t;
            const float* F = fW1 + h * 128 * 128;
            for (int k = 0; k < 128; k++) s += b2[k] * F[k * 128 + e];
        }
        g_bb[side * 128 + e] = s;
    }
}

// ================= K2: reduce 16 chunks + bias + relu -> P1 =================
__global__ __launch_bounds__(256) void k_red1(
    const float* __restrict__ b_it, const float* __restrict__ b_inw,
    const float* __restrict__ b_t2n, const float* __restrict__ b_n2t)
{
    int head = blockIdx.y;
    int i4 = blockIdx.x * 256 + threadIdx.x;   // < 4096 float4s per head
    const float* b = (head == 0) ? b_it : (head == 1) ? b_inw : (head == 2) ? b_t2n : b_n2t;
    float4 s = ((const float4*)b)[i4 & 31];
#pragma unroll
    for (int c = 0; c < 16; c++) {
        float4 p = ((const float4*)g_part1)[(size_t)(head * 16 + c) * 4096 + i4];
        s.x += p.x; s.y += p.y; s.z += p.z; s.w += p.w;
    }
    s.x = fmaxf(s.x, 0.f); s.y = fmaxf(s.y, 0.f); s.z = fmaxf(s.z, 0.f); s.w = fmaxf(s.w, 0.f);
    ((float4*)g_P1)[head * 4096 + i4] = s;
}

// ================= K3: split-K partials of G = sum_h P1_h @ WF_h =================
// grid (2 m-tiles, 4 chunks, 2 sides); chunk c: head = side + (c>>1)*2, kOff = (c&1)*64
__global__ __launch_bounds__(256) void k_G()
{
    __shared__ __align__(16) float sA[16 * 68];
    __shared__ __align__(16) float sB[16 * 128];
    int side = blockIdx.z, chunk = blockIdx.y;
    int head = side + (chunk >> 1) * 2;
    int kOff = (chunk & 1) * 64;
    int mBase = blockIdx.x * 64;
    const float* A = g_P1 + head * 16384;
    const float* B = g_WF + head * 16384;
    int tid = threadIdx.x, tx = tid & 15, ty = tid >> 4;
    u64 acc[4][4] = {};
    float4 ra = ldgA64(A, 128, mBase, kOff, tid);
    float4 rb0, rb1; ldgB(B, 128, kOff, tid, rb0, rb1);
    for (int s = 0; s < 4; s++) {
        __syncthreads();
        stsA64(sA, tid, ra); stsB(sB, tid, rb0, rb1);
        __syncthreads();
        if (s < 3) { ra = ldgA64(A, 128, mBase, kOff + (s + 1) * 16, tid); ldgB(B, 128, kOff + (s + 1) * 16, tid, rb0, rb1); }
        comp64(sA, sB, acc, tx, ty);
    }
    float* C = g_part1 + (size_t)(side * 4 + chunk) * 16384;
    int r0 = mBase + ty * 4;
#pragma unroll
    for (int u = 0; u < 4; u++) {
        *(float4*)(C + (r0 + u) * 128 + tx * 4)      = accrow(acc[u][0], acc[u][1]);
        *(float4*)(C + (r0 + u) * 128 + 64 + tx * 4) = accrow(acc[u][2], acc[u][3]);
    }
}

// ================= K4: G = sum 4 chunks + bb =================
__global__ __launch_bounds__(256) void k_redG()
{
    int side = blockIdx.y;
    int i4 = blockIdx.x * 256 + threadIdx.x;   // < 4096
    float4 s = ((const float4*)(g_bb + side * 128))[i4 & 31];
#pragma unroll
    for (int c = 0; c < 4; c++) {
        float4 p = ((const float4*)g_part1)[(size_t)(side * 4 + c) * 4096 + i4];
        s.x += p.x; s.y += p.y; s.z += p.z; s.w += p.w;
    }
    ((float4*)g_G)[side * 4096 + i4] = s;
}

// ================= K5: Htmp = relu(xt@G0 + xn@G1 + fb1) (BM=32) =================
__global__ __launch_bounds__(256) void k_Htmp(
    const float* __restrict__ xt, const float* __restrict__ xn,
    const float* __restrict__ fb1)
{
    __shared__ __align__(16) float sA[16 * 36];
    __shared__ __align__(16) float sB[16 * 128];
    int rowBase = blockIdx.x * 32;
    int tid = threadIdx.x, tx = tid & 15, ty = tid >> 4;
    u64 acc[2][4] = {};
#pragma unroll
    for (int pass = 0; pass < 2; pass++) {
        const float* A = pass ? xn : xt;
        const float* B = g_G + pass * 16384;
        float4 ra; if (tid < 128) ra = ldgA32(A, 128, rowBase, 0, tid);
        float4 rb0, rb1; ldgB(B, 128, 0, tid, rb0, rb1);
        for (int s = 0; s < 8; s++) {
            __syncthreads();
            if (tid < 128) stsA32(sA, tid, ra);
            stsB(sB, tid, rb0, rb1);
            __syncthreads();
            if (s < 7) { if (tid < 128) ra = ldgA32(A, 128, rowBase, (s + 1) * 16, tid); ldgB(B, 128, (s + 1) * 16, tid, rb0, rb1); }
            comp32(sA, sB, acc, tx, ty);
        }
        __syncthreads();
    }
    float4 bb0 = *(const float4*)(fb1 + tx * 4);
    float4 bb1 = *(const float4*)(fb1 + 64 + tx * 4);
    int r0 = rowBase + ty * 2;
#pragma unroll
    for (int u = 0; u < 2; u++) {
        float4 v0 = accrow(acc[u][0], acc[u][1]);
        float4 v1 = accrow(acc[u][2], acc[u][3]);
        v0.x = fmaxf(v0.x + bb0.x, 0.f); v0.y = fmaxf(v0.y + bb0.y, 0.f);
        v0.z = fmaxf(v0.z + bb0.z, 0.f); v0.w = fmaxf(v0.w + bb0.w, 0.f);
        v1.x = fmaxf(v1.x + bb1.x, 0.f); v1.y = fmaxf(v1.y + bb1.y, 0.f);
        v1.z = fmaxf(v1.z + bb1.z, 0.f); v1.w = fmaxf(v1.w + bb1.w, 0.f);
        *(float4*)(g_Htmp + (size_t)(r0 + u) * 128 + tx * 4) = v0;
        *(float4*)(g_Htmp + (size_t)(r0 + u) * 128 + 64 + tx * 4) = v1;
    }
}

// ================= K6: Hraw = Htmp @ f_W2 + f_b2 (BM=32) =================
__global__ __launch_bounds__(256) void k_f2(
    const float* __restrict__ fW2, const float* __restrict__ fb2)
{
    __shared__ __align__(16) float sA[16 * 36];
    __shared__ __align__(16) float sB[16 * 128];
    int rowBase = blockIdx.x * 32;
    int tid = threadIdx.x, tx = tid & 15, ty = tid >> 4;
    u64 acc[2][4] = {};
    float4 ra; if (tid < 128) ra = ldgA32(g_Htmp, 128, rowBase, 0, tid);
    float4 rb0, rb1; ldgB(fW2, 128, 0, tid, rb0, rb1);
    for (int s = 0; s < 8; s++) {
        __syncthreads();
        if (tid < 128) stsA32(sA, tid, ra);
        stsB(sB, tid, rb0, rb1);
        __syncthreads();
        if (s < 7) { if (tid < 128) ra = ldgA32(g_Htmp, 128, rowBase, (s + 1) * 16, tid); ldgB(fW2, 128, (s + 1) * 16, tid, rb0, rb1); }
        comp32(sA, sB, acc, tx, ty);
    }
    float4 bb0 = *(const float4*)(fb2 + tx * 4);
    float4 bb1 = *(const float4*)(fb2 + 64 + tx * 4);
    int r0 = rowBase + ty * 2;
#pragma unroll
    for (int u = 0; u < 2; u++) {
        float4 v0 = accrow(acc[u][0], acc[u][1]);
        float4 v1 = accrow(acc[u][2], acc[u][3]);
        v0.x += bb0.x; v0.y += bb0.y; v0.z += bb0.z; v0.w += bb0.w;
        v1.x += bb1.x; v1.y += bb1.y; v1.z += bb1.z; v1.w += bb1.w;
        *(float4*)(g_Hraw + (size_t)(r0 + u) * 128 + tx * 4) = v0;
        *(float4*)(g_Hraw + (size_t)(r0 + u) * 128 + 64 + tx * 4) = v1;
    }
}

// ================= K7: per-column standardize + softmax -> H, logH =================
__global__ __launch_bounds__(256) void k_colsm()
{
    int e = blockIdx.x;
    __shared__ float s[NTOT];
    int tid = threadIdx.x;
    for (int n = tid; n < NTOT; n += 256) s[n] = g_Hraw[n * 128 + e];
    __syncthreads();

    float lsum = 0.f;
    for (int n = tid; n < NTOT; n += 256) lsum += s[n];
    float mean = block_sum<8>(lsum) * (1.f / NTOT);

    float lss = 0.f;
    for (int n = tid; n < NTOT; n += 256) { float d = s[n] - mean; lss += d * d; }
    float var = block_sum<8>(lss) * (1.f / (NTOT - 1));
    float inv = 1.f / (sqrtf(var) + EPSV);

    float lmax = -3.4e38f;
    for (int n = tid; n < NTOT; n += 256) {
        float z = (s[n] - mean) * inv;
        s[n] = z;
        lmax = fmaxf(lmax, z);
    }
    __syncthreads();
    float mx = block_max<8>(lmax);

    float lse = 0.f;
    for (int n = tid; n < NTOT; n += 256) lse += __expf(s[n] - mx);
    float sum = block_sum<8>(lse);
    float invs = 1.f / sum;
    float lls = __logf(sum);

    for (int n = tid; n < NTOT; n += 256) {
        float z = s[n];
        g_H[n * 128 + e]    = __expf(z - mx) * invs;
        g_logH[n * 128 + e] = (z - mx) - lls;
    }
}

// ================= stageB: partZ(128 CTAs) + jsd(288 CTAs) in ONE launch =================
__global__ __launch_bounds__(256) void k_stageB()
{
    __shared__ __align__(16) float smem[3136];
    int tid = threadIdx.x;
    int bx = blockIdx.x;

    if (bx < 128) {
        // ---- partZ: split-K partials of Z = H^T @ Y ----
        int side = bx >> 6;
        int r = bx & 63;
        int mBase = (r & 1) * 64;
        int kBeg = (r >> 1) * 64;
        float* sA = smem;             // 16*68
        float* sB = smem + 1088;      // 16*128
        const float* B = g_Y + (size_t)side * NTOT * 128;
        int tx = tid & 15, ty = tid >> 4;
        u64 acc[4][4] = {};
        float4 ra = ldgAt(g_H, mBase, kBeg, tid);
        float4 rb0, rb1; ldgB(B, 128, kBeg, tid, rb0, rb1);
        for (int s = 0; s < 4; s++) {
            __syncthreads();
            stsAt(sA, tid, ra); stsB(sB, tid, rb0, rb1);
            __syncthreads();
            if (s < 3) { ra = ldgAt(g_H, mBase, kBeg + (s + 1) * 16, tid); ldgB(B, 128, kBeg + (s + 1) * 16, tid, rb0, rb1); }
            comp64(sA, sB, acc, tx, ty);
        }
        float* C = g_partZ + (size_t)(side * 32 + (r >> 1)) * 16384;
        int r0 = mBase + ty * 4;
#pragma unroll
        for (int u = 0; u < 4; u++) {
            *(float4*)(C + (r0 + u) * 128 + tx * 4)      = accrow(acc[u][0], acc[u][1]);
            *(float4*)(C + (r0 + u) * 128 + 64 + tx * 4) = accrow(acc[u][2], acc[u][3]);
        }
    } else {
        // ---- jsd tile ----
        int idx = bx - 128;           // 0..287
        int t = idx % 36;
        int nch = idx / 36;           // 0..7
        int bi = 0, rem = t;
        while (rem >= 8 - bi) { rem -= 8 - bi; bi++; }
        int bj = bi + rem;
        int ti = tid & 15, tj = tid >> 4;
        int i = bi * 16 + ti, j = bj * 16 + tj;

        float* sHi = smem;
        float* sLi = smem + 256;
        float* sHj = smem + 512;
        float* sLj = smem + 768;
        float* red = smem + 1024;

        float acci = 0.f, accj = 0.f;
        int lr = tid >> 4, lc = tid & 15;
        int nBeg = nch * 256;

        for (int n0 = nBeg; n0 < nBeg + 256; n0 += 16) {
            __syncthreads();
            int n = n0 + lr;
            sHi[lr * 16 + lc] = g_H   [n * 128 + bi * 16 + lc];
            sLi[lr * 16 + lc] = g_logH[n * 128 + bi * 16 + lc];
            sHj[lr * 16 + lc] = g_H   [n * 128 + bj * 16 + lc];
            sLj[lr * 16 + lc] = g_logH[n * 128 + bj * 16 + lc];
            __syncthreads();
#pragma unroll
            for (int r2 = 0; r2 < 16; r2++) {
                float hi = sHi[r2 * 16 + ti], hj = sHj[r2 * 16 + tj];
                float m  = 0.5f * (hi + hj);
                float lm = __logf(m);
                acci += hi * (sLi[r2 * 16 + ti] - lm);
                accj += hj * (sLj[r2 * 16 + tj] - lm);
            }
        }
        float v = (i < j) ? 0.5f * (acci + accj) : 0.f;

        __syncthreads();
        red[tj * 16 + ti] = v;
        __syncthreads();

        float* out = g_jpart + (size_t)(nch * 36 + t) * 128;
        if (tid < 128) out[tid] = 0.f;
        __syncthreads();
        if (tid < 16) {
            float si = 0.f, sj = 0.f;
#pragma unroll
            for (int r2 = 0; r2 < 16; r2++) { si += red[r2 * 16 + tid]; sj += red[tid * 16 + r2]; }
            out[bi * 16 + tid] += si;
            out[bj * 16 + tid] += sj;
        }
    }
}

// ================= K9: jm -> standardized -> softmax -> w =================
__global__ __launch_bounds__(128) void k_w()
{
    int e = threadIdx.x;
    float cs = 0.f;
    for (int r = 0; r < JROWS; r++) cs += g_jpart[r * 128 + e];
    float jm = cs * (1.f / 128.f);

    float mean = block_sum<4>(jm) * (1.f / 128.f);
    float d = jm - mean;
    float var = block_sum<4>(d * d) * (1.f / 127.f);
    float njm = d / (sqrtf(var) + EPSV);

    float mx = block_max<4>(njm);
    float ex = __expf(njm - mx);
    float sum = block_sum<4>(ex);
    g_w[e] = ex / sum;
}

// ================= K12: Zw = w * (sum chunks) =================
__global__ __launch_bounds__(256) void k_redZ()
{
    int side = blockIdx.y;
    int i4 = blockIdx.x * 256 + threadIdx.x;   // < 4096
    float4 s = make_float4(0.f, 0.f, 0.f, 0.f);
#pragma unroll
    for (int c = 0; c < 32; c++) {
        float4 p = ((const float4*)g_partZ)[(size_t)(side * 32 + c) * 4096 + i4];
        s.x += p.x; s.y += p.y; s.z += p.z; s.w += p.w;
    }
    float wv = g_w[i4 >> 5];
    s.x *= wv; s.y *= wv; s.z *= wv; s.w *= wv;
    ((float4*)g_Zw)[side * 4096 + i4] = s;
}

// ================= K13: out = x + elu(H @ Zw) (BM=32) =================
__global__ __launch_bounds__(256) void k_final(
    const float* __restrict__ xt, const float* __restrict__ xn,
    float* __restrict__ out)
{
    __shared__ __align__(16) float sA[16 * 36];
    __shared__ __align__(16) float sB[16 * 128];
    int side = blockIdx.z;
    const float* x = side ? xn : xt;
    const float* B = g_Zw + side * 16384;
    int rowBase = blockIdx.x * 32;
    int tid = threadIdx.x, tx = tid & 15, ty = tid >> 4;
    u64 acc[2][4] = {};
    float4 ra; if (tid < 128) ra = ldgA32(g_H, 128, rowBase, 0, tid);
    float4 rb0, rb1; ldgB(B, 128, 0, tid, rb0, rb1);
    for (int s = 0; s < 8; s++) {
        __syncthreads();
        if (tid < 128) stsA32(sA, tid, ra);
        stsB(sB, tid, rb0, rb1);
        __syncthreads();
        if (s < 7) { if (tid < 128) ra = ldgA32(g_H, 128, rowBase, (s + 1) * 16, tid); ldgB(B, 128, (s + 1) * 16, tid, rb0, rb1); }
        comp32(sA, sB, acc, tx, ty);
    }
    float* o = out + (size_t)side * NTOT * 128;
    int r0 = rowBase + ty * 2;
#pragma unroll
    for (int u = 0; u < 2; u++) {
#pragma unroll
        for (int h = 0; h < 2; h++) {
            float4 v = accrow(acc[u][h * 2], acc[u][h * 2 + 1]);
            int c = h * 64 + tx * 4;
            float4 xv = *(const float4*)(x + (size_t)(r0 + u) * 128 + c);
            v.x = xv.x + ((v.x > 0.f) ? v.x : expm1f(v.x));
            v.y = xv.y + ((v.y > 0.f) ? v.y : expm1f(v.y));
            v.z = xv.z + ((v.z > 0.f) ? v.z : expm1f(v.z));
            v.w = xv.w + ((v.w > 0.f) ? v.w : expm1f(v.w));
            *(float4*)(o + (size_t)(r0 + u) * 128 + c) = v;
        }
    }
}

// ---------------- launch ----------------
extern "C" void kernel_launch(void* const* d_in, const int* in_sizes, int n_in,
                              void* d_out, int out_size)
{
    const float* xt    = (const float*)d_in[0];
    const float* xn    = (const float*)d_in[1];
    const float* itW1  = (const float*)d_in[2];
    const float* itb1  = (const float*)d_in[3];
    const float* itW2  = (const float*)d_in[4];
    const float* itb2  = (const float*)d_in[5];
    const float* inwW1 = (const float*)d_in[6];
    const float* inwb1 = (const float*)d_in[7];
    const float* inwW2 = (const float*)d_in[8];
    const float* inwb2 = (const float*)d_in[9];
    const float* t2nW1 = (const float*)d_in[10];
    const float* t2nb1 = (const float*)d_in[11];
    const float* t2nW2 = (const float*)d_in[12];
    const float* t2nb2 = (const float*)d_in[13];
    const float* n2tW1 = (const float*)d_in[14];
    const float* n2tb1 = (const float*)d_in[15];
    const float* n2tW2 = (const float*)d_in[16];
    const float* n2tb2 = (const float*)d_in[17];
    const float* fW1   = (const float*)d_in[18];
    const float* fb1   = (const float*)d_in[19];
    const float* fW2   = (const float*)d_in[20];
    const float* fb2   = (const float*)d_in[21];
    const float* thT   = (const float*)d_in[22];
    const float* thN   = (const float*)d_in[23];
    float* out = (float*)d_out;

    k_stageA<<<209, 256>>>(xt, xn, itW1, inwW1, t2nW1, n2tW1, thT, thN,
                           itW2, inwW2, t2nW2, n2tW2, fW1,
                           itb2, inwb2, t2nb2, n2tb2);
    k_red1 <<<dim3(16, 4), 256>>>(itb1, inwb1, t2nb1, n2tb1);
    k_G    <<<dim3(2, 4, 2), 256>>>();
    k_redG <<<dim3(16, 2), 256>>>();
    k_Htmp <<<64, 256>>>(xt, xn, fb1);
    k_f2   <<<64, 256>>>(fW2, fb2);
    k_colsm<<<128, 256>>>();
    k_stageB<<<416, 256>>>();
    k_w    <<<1, 128>>>();
    k_redZ <<<dim3(16, 2), 256>>>();
    k_final<<<dim3(64, 1, 2), 256>>>(xt, xn, out);
}